// round 7
// baseline (speedup 1.0000x reference)
#include <cuda_runtime.h>
#include <cuda_fp16.h>

#define NLEV 16
#define NSIDE 512
#define NN (NSIDE * NSIDE)
#define THREADS 512
#define NPTS 1048576
#define NB 256
#define NBINS (NB * NB)
#define PPT 4   // points per thread in hist/scatter

__device__ __align__(16) uint4 g_quad[NLEV * NN];

__device__ int   g_hist[NBINS];
__device__ int   g_offs[NBINS];
__device__ __align__(16) uint4 g_pack[NPTS];   // {px, py, orig_idx, pad}

__device__ __constant__ float c_scaler[NLEV] = {
     16.0f/512.0f,  20.0f/512.0f,  25.0f/512.0f,  32.0f/512.0f,
     40.0f/512.0f,  50.0f/512.0f,  64.0f/512.0f,  80.0f/512.0f,
    101.0f/512.0f, 128.0f/512.0f, 161.0f/512.0f, 203.0f/512.0f,
    256.0f/512.0f, 322.0f/512.0f, 406.0f/512.0f, 512.0f/512.0f
};

__global__ void __launch_bounds__(256)
quadify_kernel(const float* __restrict__ table)
{
    int i = blockIdx.x * 256 + threadIdx.x;
    if (i >= NLEV * NN) return;
    const int l  = i >> 18;
    const int p  = i & (NN - 1);
    const int xx = p & (NSIDE - 1);
    const int yy = p >> 9;

    const float* t0 = table + (size_t)(2 * l) * NN;
    const float* t1 = t0 + NN;

    const bool xe = (xx < NSIDE - 1);
    const bool ye = (yy < NSIDE - 1);

    float a0 = t0[p],                     a1 = t1[p];
    float b0 = xe ? t0[p + 1] : 0.0f,     b1 = xe ? t1[p + 1] : 0.0f;
    float c0 = ye ? t0[p + NSIDE] : 0.0f, c1 = ye ? t1[p + NSIDE] : 0.0f;
    float d0 = (xe && ye) ? t0[p + NSIDE + 1] : 0.0f;
    float d1 = (xe && ye) ? t1[p + NSIDE + 1] : 0.0f;

    __half2 ha = __floats2half2_rn(a0, a1);
    __half2 hb = __floats2half2_rn(b0, b1);
    __half2 hc = __floats2half2_rn(c0, c1);
    __half2 hd = __floats2half2_rn(d0, d1);
    uint4 e;
    e.x = *reinterpret_cast<unsigned*>(&ha);
    e.y = *reinterpret_cast<unsigned*>(&hb);
    e.z = *reinterpret_cast<unsigned*>(&hc);
    e.w = *reinterpret_cast<unsigned*>(&hd);
    g_quad[i] = e;
}

__device__ __forceinline__ unsigned part1by1(unsigned v) {
    v &= 0xFF;
    v = (v | (v << 4)) & 0x0F0F;
    v = (v | (v << 2)) & 0x3333;
    v = (v | (v << 1)) & 0x5555;
    return v;
}

__device__ __forceinline__ int point_bin(float px, float py) {
    int bx = (int)((px + 1.0f) * (NB * 0.5f));
    int by = (int)((py + 1.0f) * (NB * 0.5f));
    bx = min(max(bx, 0), NB - 1);
    by = min(max(by, 0), NB - 1);
    return (int)((part1by1((unsigned)by) << 1) | part1by1((unsigned)bx));
}

// 4 points per thread, coalesced float4 reads, independent atomics (MLP=4).
__global__ void __launch_bounds__(THREADS)
hist_kernel(const float4* __restrict__ x2)
{
    const int base = blockIdx.x * THREADS * (PPT / 2) + threadIdx.x;
    #pragma unroll
    for (int k = 0; k < PPT / 2; k++) {
        float4 v = x2[base + k * THREADS];
        atomicAdd(&g_hist[point_bin(v.x, v.y)], 1);
        atomicAdd(&g_hist[point_bin(v.z, v.w)], 1);
    }
}

__global__ void __launch_bounds__(1024)
scan_kernel()
{
    __shared__ int s[1024];
    const int t = threadIdx.x;
    const int C = NBINS / 1024;            // 64 bins per thread
    const int base = t * C;
    int sum = 0;
    for (int j = 0; j < C; j++) sum += g_hist[base + j];
    s[t] = sum;
    __syncthreads();
    #pragma unroll
    for (int d = 1; d < 1024; d <<= 1) {
        int v = (t >= d) ? s[t - d] : 0;
        __syncthreads();
        if (t >= d) s[t] += v;
        __syncthreads();
    }
    int run = s[t] - sum;                  // exclusive prefix of this chunk
    for (int j = 0; j < C; j++) { int h = g_hist[base + j]; g_offs[base + j] = run; run += h; }
}

__global__ void __launch_bounds__(THREADS)
scatter_kernel(const float4* __restrict__ x2)
{
    const int base2 = blockIdx.x * THREADS * (PPT / 2) + threadIdx.x;
    #pragma unroll
    for (int k = 0; k < PPT / 2; k++) {
        const float4 v   = x2[base2 + k * THREADS];
        const int   gid0 = (base2 + k * THREADS) * 2;
        const int pos0 = atomicAdd(&g_offs[point_bin(v.x, v.y)], 1);
        const int pos1 = atomicAdd(&g_offs[point_bin(v.z, v.w)], 1);
        uint4 r0, r1;
        r0.x = __float_as_uint(v.x); r0.y = __float_as_uint(v.y);
        r0.z = (unsigned)gid0;       r0.w = 0u;
        r1.x = __float_as_uint(v.z); r1.y = __float_as_uint(v.w);
        r1.z = (unsigned)(gid0 + 1); r1.w = 0u;
        g_pack[pos0] = r0;
        g_pack[pos1] = r1;
    }
}

__device__ __forceinline__ float2 h2f(unsigned u) {
    return __half22float2(*reinterpret_cast<__half2*>(&u));
}

__global__ void __launch_bounds__(THREADS, 3)
grid_linear_kernel(float* __restrict__ out)
{
    extern __shared__ float tr[];   // 16 warps x 32 x 33 floats

    const int tid  = threadIdx.x;
    const int warp = tid >> 5;
    const int lane = tid & 31;
    const int gid  = blockIdx.x * THREADS + tid;

    const uint4 rec = g_pack[gid];
    const float2 p  = make_float2(__uint_as_float(rec.x), __uint_as_float(rec.y));
    const int    oi = (int)rec.z;

    float* rowbuf = tr + warp * (32 * 33) + lane * 33;

    // Levels 0..14: one LDG.128 quad per level; results straight to smem.
    #pragma unroll
    for (int l = 0; l < 15; l++) {
        const float s  = c_scaler[l];
        const float ix = ((p.x * s + 1.0f) * 512.0f - 1.0f) * 0.5f;
        const float iy = ((p.y * s + 1.0f) * 512.0f - 1.0f) * 0.5f;

        const float x0f = floorf(ix);
        const float y0f = floorf(iy);
        const float wx1 = ix - x0f;
        const float wy1 = iy - y0f;
        const float wx0 = 1.0f - wx1;
        const float wy0 = 1.0f - wy1;

        const int x0 = (int)x0f;
        const int y0 = (int)y0f;

        const uint4 q = __ldg(g_quad + (size_t)l * NN + (y0 * NSIDE + x0));
        const float2 a00 = h2f(q.x), a01 = h2f(q.y);
        const float2 a10 = h2f(q.z), a11 = h2f(q.w);

        const float w00 = wx0 * wy0, w01 = wx1 * wy0;
        const float w10 = wx0 * wy1, w11 = wx1 * wy1;

        rowbuf[l]      = a00.x * w00 + a01.x * w01 + a10.x * w10 + a11.x * w11;
        rowbuf[16 + l] = a00.y * w00 + a01.y * w01 + a10.y * w10 + a11.y * w11;
    }

    // Level 15: clamping + validity; lo half2 of quad entries.
    {
        const float ix = ((p.x + 1.0f) * 512.0f - 1.0f) * 0.5f;
        const float iy = ((p.y + 1.0f) * 512.0f - 1.0f) * 0.5f;

        const float x0f = floorf(ix);
        const float y0f = floorf(iy);
        const float wx1 = ix - x0f;
        const float wy1 = iy - y0f;
        const float wx0 = 1.0f - wx1;
        const float wy0 = 1.0f - wy1;

        const int x0 = (int)x0f, y0 = (int)y0f;
        const int x1 = x0 + 1,   y1 = y0 + 1;

        const float vx0 = (x0 >= 0 && x0 < NSIDE) ? 1.0f : 0.0f;
        const float vx1 = (x1 >= 0 && x1 < NSIDE) ? 1.0f : 0.0f;
        const float vy0 = (y0 >= 0 && y0 < NSIDE) ? 1.0f : 0.0f;
        const float vy1 = (y1 >= 0 && y1 < NSIDE) ? 1.0f : 0.0f;

        const int xc0 = min(max(x0, 0), NSIDE - 1);
        const int xc1 = min(max(x1, 0), NSIDE - 1);
        const int yc0 = min(max(y0, 0), NSIDE - 1);
        const int yc1 = min(max(y1, 0), NSIDE - 1);

        const unsigned* t = (const unsigned*)(g_quad + (size_t)15 * NN);
        const float2 a00 = h2f(__ldg(t + (yc0 * NSIDE + xc0) * 4));
        const float2 a01 = h2f(__ldg(t + (yc0 * NSIDE + xc1) * 4));
        const float2 a10 = h2f(__ldg(t + (yc1 * NSIDE + xc0) * 4));
        const float2 a11 = h2f(__ldg(t + (yc1 * NSIDE + xc1) * 4));

        const float w00 = wx0 * wy0 * (vx0 * vy0);
        const float w01 = wx1 * wy0 * (vx1 * vy0);
        const float w10 = wx0 * wy1 * (vx0 * vy1);
        const float w11 = wx1 * wy1 * (vx1 * vy1);

        rowbuf[15] = a00.x * w00 + a01.x * w01 + a10.x * w10 + a11.x * w11;
        rowbuf[31] = a00.y * w00 + a01.y * w01 + a10.y * w10 + a11.y * w11;
    }

    __syncwarp();

    #pragma unroll
    for (int r = 0; r < 32; r++) {
        const int ir = __shfl_sync(0xffffffffu, oi, r);
        __stcs(out + (size_t)ir * 32 + lane, tr[warp * (32 * 33) + r * 33 + lane]);
    }
}

extern "C" void kernel_launch(void* const* d_in, const int* in_sizes, int n_in,
                              void* d_out, int out_size)
{
    const float2* x     = (const float2*)d_in[0];
    const float*  table = (const float*)d_in[1];
    float*        out   = (float*)d_out;

    static void* hist_addr = nullptr;
    static cudaStream_t s1;
    static cudaEvent_t ev_fork, ev_quad;
    static int init_done = 0;
    if (!init_done) {
        cudaGetSymbolAddress(&hist_addr, g_hist);
        cudaFuncSetAttribute(grid_linear_kernel,
                             cudaFuncAttributeMaxDynamicSharedMemorySize,
                             16 * 32 * 33 * (int)sizeof(float));
        cudaStreamCreateWithFlags(&s1, cudaStreamNonBlocking);
        cudaEventCreateWithFlags(&ev_fork, cudaEventDisableTiming);
        cudaEventCreateWithFlags(&ev_quad, cudaEventDisableTiming);
        init_done = 1;
    }

    // Fork: quadify on side stream; sort chain on main stream.
    cudaEventRecord(ev_fork, 0);
    cudaStreamWaitEvent(s1, ev_fork, 0);
    quadify_kernel<<<(NLEV * NN + 255) / 256, 256, 0, s1>>>(table);
    cudaEventRecord(ev_quad, s1);

    cudaMemsetAsync(hist_addr, 0, NBINS * sizeof(int));
    hist_kernel<<<NPTS / (THREADS * PPT), THREADS>>>((const float4*)x);
    scan_kernel<<<1, 1024>>>();
    scatter_kernel<<<NPTS / (THREADS * PPT), THREADS>>>((const float4*)x);

    cudaStreamWaitEvent(0, ev_quad, 0);
    grid_linear_kernel<<<NPTS / THREADS, THREADS, 16 * 32 * 33 * sizeof(float)>>>(out);
}

// round 8
// speedup vs baseline: 1.7963x; 1.7963x over previous
#include <cuda_runtime.h>
#include <cuda_fp16.h>

#define NLEV 16
#define NSIDE 512
#define NN (NSIDE * NSIDE)
#define THREADS 512
#define NPTS 1048576
#define NB 128
#define NBINS (NB * NB)
#define PPT 4

__device__ __align__(16) uint4 g_quad[NLEV * NN];

__device__ int   g_hist[NBINS];
__device__ int   g_offs[NBINS];
__device__ __align__(16) uint4 g_pack[NPTS];   // {px, py, orig_idx, pad}

// A_l = 256 * scaler_l ; ix = fmaf(px, A_l, 255.5f)
__device__ __constant__ float c_A[NLEV] = {
      8.0f,  10.0f,  12.5f,  16.0f,  20.0f,  25.0f,  32.0f,  40.0f,
     50.5f,  64.0f,  80.5f, 101.5f, 128.0f, 161.0f, 203.0f, 256.0f
};

__global__ void __launch_bounds__(256)
quadify_kernel(const float* __restrict__ table)
{
    int i = blockIdx.x * 256 + threadIdx.x;
    if (i >= NLEV * NN) return;
    const int l  = i >> 18;
    const int p  = i & (NN - 1);
    const int xx = p & (NSIDE - 1);
    const int yy = p >> 9;

    const float* t0 = table + (size_t)(2 * l) * NN;
    const float* t1 = t0 + NN;

    const bool xe = (xx < NSIDE - 1);
    const bool ye = (yy < NSIDE - 1);

    float a0 = t0[p],                     a1 = t1[p];
    float b0 = xe ? t0[p + 1] : 0.0f,     b1 = xe ? t1[p + 1] : 0.0f;
    float c0 = ye ? t0[p + NSIDE] : 0.0f, c1 = ye ? t1[p + NSIDE] : 0.0f;
    float d0 = (xe && ye) ? t0[p + NSIDE + 1] : 0.0f;
    float d1 = (xe && ye) ? t1[p + NSIDE + 1] : 0.0f;

    __half2 ha = __floats2half2_rn(a0, a1);
    __half2 hb = __floats2half2_rn(b0, b1);
    __half2 hc = __floats2half2_rn(c0, c1);
    __half2 hd = __floats2half2_rn(d0, d1);
    uint4 e;
    e.x = *reinterpret_cast<unsigned*>(&ha);
    e.y = *reinterpret_cast<unsigned*>(&hb);
    e.z = *reinterpret_cast<unsigned*>(&hc);
    e.w = *reinterpret_cast<unsigned*>(&hd);
    g_quad[i] = e;
}

__device__ __forceinline__ int point_bin(float px, float py) {
    int bx = (int)((px + 1.0f) * (NB * 0.5f));
    int by = (int)((py + 1.0f) * (NB * 0.5f));
    bx = min(max(bx, 0), NB - 1);
    by = min(max(by, 0), NB - 1);
    return by * NB + bx;
}

__global__ void __launch_bounds__(THREADS)
hist_kernel(const float4* __restrict__ x2)
{
    const int base = blockIdx.x * THREADS * (PPT / 2) + threadIdx.x;
    #pragma unroll
    for (int k = 0; k < PPT / 2; k++) {
        float4 v = x2[base + k * THREADS];
        atomicAdd(&g_hist[point_bin(v.x, v.y)], 1);
        atomicAdd(&g_hist[point_bin(v.z, v.w)], 1);
    }
}

__global__ void __launch_bounds__(1024)
scan_kernel()
{
    __shared__ int s[1024];
    const int t = threadIdx.x;
    const int C = NBINS / 1024;            // 16 bins per thread
    const int base = t * C;
    int local[C];
    int sum = 0;
    #pragma unroll
    for (int j = 0; j < C; j++) { local[j] = g_hist[base + j]; sum += local[j]; }
    s[t] = sum;
    __syncthreads();
    #pragma unroll
    for (int d = 1; d < 1024; d <<= 1) {
        int v = (t >= d) ? s[t - d] : 0;
        __syncthreads();
        if (t >= d) s[t] += v;
        __syncthreads();
    }
    int run = s[t] - sum;
    #pragma unroll
    for (int j = 0; j < C; j++) { g_offs[base + j] = run; run += local[j]; }
}

__global__ void __launch_bounds__(THREADS)
scatter_kernel(const float4* __restrict__ x2)
{
    const int base2 = blockIdx.x * THREADS * (PPT / 2) + threadIdx.x;
    #pragma unroll
    for (int k = 0; k < PPT / 2; k++) {
        const float4 v   = x2[base2 + k * THREADS];
        const int   gid0 = (base2 + k * THREADS) * 2;
        const int pos0 = atomicAdd(&g_offs[point_bin(v.x, v.y)], 1);
        const int pos1 = atomicAdd(&g_offs[point_bin(v.z, v.w)], 1);
        uint4 r0, r1;
        r0.x = __float_as_uint(v.x); r0.y = __float_as_uint(v.y);
        r0.z = (unsigned)gid0;       r0.w = 0u;
        r1.x = __float_as_uint(v.z); r1.y = __float_as_uint(v.w);
        r1.z = (unsigned)(gid0 + 1); r1.w = 0u;
        g_pack[pos0] = r0;
        g_pack[pos1] = r1;
    }
}

__device__ __forceinline__ float2 h2f(unsigned u) {
    return __half22float2(*reinterpret_cast<__half2*>(&u));
}

__global__ void __launch_bounds__(THREADS, 2)
grid_linear_kernel(float* __restrict__ out)
{
    extern __shared__ float tr[];   // 16 warps x 32 x 33 floats

    const int tid  = threadIdx.x;
    const int warp = tid >> 5;
    const int lane = tid & 31;
    const int gid  = blockIdx.x * THREADS + tid;

    const uint4 rec = g_pack[gid];
    const float2 p  = make_float2(__uint_as_float(rec.x), __uint_as_float(rec.y));
    const int    oi = (int)rec.z;

    float res[32];

    // Levels 0..14: one LDG.128 quad per level; register results preserve MLP.
    #pragma unroll
    for (int l = 0; l < 15; l++) {
        const float ix = fmaf(p.x, c_A[l], 255.5f);
        const float iy = fmaf(p.y, c_A[l], 255.5f);

        const float x0f = floorf(ix);
        const float y0f = floorf(iy);
        const float wx1 = ix - x0f;
        const float wy1 = iy - y0f;
        const float wx0 = 1.0f - wx1;
        const float wy0 = 1.0f - wy1;

        const int x0 = (int)x0f;
        const int y0 = (int)y0f;

        const uint4 q = __ldg(g_quad + (size_t)l * NN + (y0 * NSIDE + x0));
        const float2 a00 = h2f(q.x), a01 = h2f(q.y);
        const float2 a10 = h2f(q.z), a11 = h2f(q.w);

        const float w00 = wx0 * wy0, w01 = wx1 * wy0;
        const float w10 = wx0 * wy1, w11 = wx1 * wy1;

        res[l]      = a00.x * w00 + a01.x * w01 + a10.x * w10 + a11.x * w11;
        res[16 + l] = a00.y * w00 + a01.y * w01 + a10.y * w10 + a11.y * w11;
    }

    // Level 15: clamping + validity; lo half2 of quad entries.
    {
        const float ix = fmaf(p.x, 256.0f, 255.5f);
        const float iy = fmaf(p.y, 256.0f, 255.5f);

        const float x0f = floorf(ix);
        const float y0f = floorf(iy);
        const float wx1 = ix - x0f;
        const float wy1 = iy - y0f;
        const float wx0 = 1.0f - wx1;
        const float wy0 = 1.0f - wy1;

        const int x0 = (int)x0f, y0 = (int)y0f;
        const int x1 = x0 + 1,   y1 = y0 + 1;

        const float vx0 = (x0 >= 0 && x0 < NSIDE) ? 1.0f : 0.0f;
        const float vx1 = (x1 >= 0 && x1 < NSIDE) ? 1.0f : 0.0f;
        const float vy0 = (y0 >= 0 && y0 < NSIDE) ? 1.0f : 0.0f;
        const float vy1 = (y1 >= 0 && y1 < NSIDE) ? 1.0f : 0.0f;

        const int xc0 = min(max(x0, 0), NSIDE - 1);
        const int xc1 = min(max(x1, 0), NSIDE - 1);
        const int yc0 = min(max(y0, 0), NSIDE - 1);
        const int yc1 = min(max(y1, 0), NSIDE - 1);

        const unsigned* t = (const unsigned*)(g_quad + (size_t)15 * NN);
        const float2 a00 = h2f(__ldg(t + (yc0 * NSIDE + xc0) * 4));
        const float2 a01 = h2f(__ldg(t + (yc0 * NSIDE + xc1) * 4));
        const float2 a10 = h2f(__ldg(t + (yc1 * NSIDE + xc0) * 4));
        const float2 a11 = h2f(__ldg(t + (yc1 * NSIDE + xc1) * 4));

        const float w00 = wx0 * wy0 * (vx0 * vy0);
        const float w01 = wx1 * wy0 * (vx1 * vy0);
        const float w10 = wx0 * wy1 * (vx0 * vy1);
        const float w11 = wx1 * wy1 * (vx1 * vy1);

        res[15] = a00.x * w00 + a01.x * w01 + a10.x * w10 + a11.x * w11;
        res[31] = a00.y * w00 + a01.y * w01 + a10.y * w10 + a11.y * w11;
    }

    // Transpose in smem, then one coalesced 128B row per original point index.
    float* rowbuf = tr + warp * (32 * 33) + lane * 33;
    #pragma unroll
    for (int i = 0; i < 32; i++) rowbuf[i] = res[i];
    __syncwarp();

    #pragma unroll
    for (int r = 0; r < 32; r++) {
        const int ir = __shfl_sync(0xffffffffu, oi, r);
        __stcs(out + (size_t)ir * 32 + lane, tr[warp * (32 * 33) + r * 33 + lane]);
    }
}

extern "C" void kernel_launch(void* const* d_in, const int* in_sizes, int n_in,
                              void* d_out, int out_size)
{
    const float2* x     = (const float2*)d_in[0];
    const float*  table = (const float*)d_in[1];
    float*        out   = (float*)d_out;

    static void* hist_addr = nullptr;
    static cudaStream_t s1;
    static cudaEvent_t ev_fork, ev_quad;
    static int init_done = 0;
    if (!init_done) {
        cudaGetSymbolAddress(&hist_addr, g_hist);
        cudaFuncSetAttribute(grid_linear_kernel,
                             cudaFuncAttributeMaxDynamicSharedMemorySize,
                             16 * 32 * 33 * (int)sizeof(float));
        cudaStreamCreateWithFlags(&s1, cudaStreamNonBlocking);
        cudaEventCreateWithFlags(&ev_fork, cudaEventDisableTiming);
        cudaEventCreateWithFlags(&ev_quad, cudaEventDisableTiming);
        init_done = 1;
    }

    // Fork: quadify on side stream; sort chain on main stream.
    cudaEventRecord(ev_fork, 0);
    cudaStreamWaitEvent(s1, ev_fork, 0);
    quadify_kernel<<<(NLEV * NN + 255) / 256, 256, 0, s1>>>(table);
    cudaEventRecord(ev_quad, s1);

    cudaMemsetAsync(hist_addr, 0, NBINS * sizeof(int));
    hist_kernel<<<NPTS / (THREADS * PPT), THREADS>>>((const float4*)x);
    scan_kernel<<<1, 1024>>>();
    scatter_kernel<<<NPTS / (THREADS * PPT), THREADS>>>((const float4*)x);

    cudaStreamWaitEvent(0, ev_quad, 0);
    grid_linear_kernel<<<NPTS / THREADS, THREADS, 16 * 32 * 33 * sizeof(float)>>>(out);
}

// round 10
// speedup vs baseline: 1.8862x; 1.0500x over previous
#include <cuda_runtime.h>
#include <cuda_fp16.h>

#define NLEV 16
#define NSIDE 512
#define NP 513            // padded side for level-15 quad table
#define NN (NSIDE * NSIDE)
#define THREADS 512
#define NPTS 1048576
#define NB 128
#define NBINS (NB * NB)
#define PPT 4

__device__ __align__(16) uint4 g_quad[15 * NN];      // levels 0..14
__device__ __align__(16) uint4 g_quad15[NP * NP];    // level 15, padded

__device__ int      g_hist[NBINS];
__device__ int      g_offs[NBINS];
__device__ unsigned g_rank[NPTS];              // bin | (rank << 14)
__device__ __align__(16) uint4 g_pack[NPTS];   // {px, py, orig_idx, pad}

// A_l = 256 * scaler_l ; ix = fmaf(px, A_l, 255.5f)
__device__ __constant__ float c_A[NLEV] = {
      8.0f,  10.0f,  12.5f,  16.0f,  20.0f,  25.0f,  32.0f,  40.0f,
     50.5f,  64.0f,  80.5f, 101.5f, 128.0f, 161.0f, 203.0f, 256.0f
};

__device__ __forceinline__ uint4 make_quad(const float* t0, const float* t1,
                                           int y0, int x0)
{
    auto val = [&](int y, int xx, const float* t) -> float {
        return (y >= 0 && y < NSIDE && xx >= 0 && xx < NSIDE) ? t[y * NSIDE + xx] : 0.0f;
    };
    __half2 ha = __floats2half2_rn(val(y0, x0, t0),         val(y0, x0, t1));
    __half2 hb = __floats2half2_rn(val(y0, x0 + 1, t0),     val(y0, x0 + 1, t1));
    __half2 hc = __floats2half2_rn(val(y0 + 1, x0, t0),     val(y0 + 1, x0, t1));
    __half2 hd = __floats2half2_rn(val(y0 + 1, x0 + 1, t0), val(y0 + 1, x0 + 1, t1));
    uint4 e;
    e.x = *reinterpret_cast<unsigned*>(&ha);
    e.y = *reinterpret_cast<unsigned*>(&hb);
    e.z = *reinterpret_cast<unsigned*>(&hc);
    e.w = *reinterpret_cast<unsigned*>(&hd);
    return e;
}

__global__ void __launch_bounds__(256)
quadify_kernel(const float* __restrict__ table)
{
    int i = blockIdx.x * 256 + threadIdx.x;
    if (i >= 15 * NN) return;
    const int l  = i >> 18;
    const int p  = i & (NN - 1);
    const float* t0 = table + (size_t)(2 * l) * NN;
    g_quad[i] = make_quad(t0, t0 + NN, p >> 9, p & (NSIDE - 1));
}

__global__ void __launch_bounds__(256)
quadify15_kernel(const float* __restrict__ table)
{
    int i = blockIdx.x * 256 + threadIdx.x;
    if (i >= NP * NP) return;
    const int yy = i / NP;
    const int xx = i - yy * NP;
    const float* t0 = table + (size_t)30 * NN;
    g_quad15[i] = make_quad(t0, t0 + NN, yy - 1, xx - 1);   // stencil at (y0,x0)=(yy-1,xx-1)
}

__device__ __forceinline__ int point_bin(float px, float py) {
    int bx = (int)((px + 1.0f) * (NB * 0.5f));
    int by = (int)((py + 1.0f) * (NB * 0.5f));
    bx = min(max(bx, 0), NB - 1);
    by = min(max(by, 0), NB - 1);
    return by * NB + bx;
}

// Pass 1: histogram + per-point rank (the atomicAdd return value).
__global__ void __launch_bounds__(THREADS)
hist_kernel(const float4* __restrict__ x2)
{
    const int base = blockIdx.x * THREADS * (PPT / 2) + threadIdx.x;
    #pragma unroll
    for (int k = 0; k < PPT / 2; k++) {
        const int   i2 = base + k * THREADS;
        const float4 v = x2[i2];
        const int b0 = point_bin(v.x, v.y);
        const int b1 = point_bin(v.z, v.w);
        const unsigned r0 = (unsigned)atomicAdd(&g_hist[b0], 1);
        const unsigned r1 = (unsigned)atomicAdd(&g_hist[b1], 1);
        g_rank[i2 * 2]     = (unsigned)b0 | (r0 << 14);
        g_rank[i2 * 2 + 1] = (unsigned)b1 | (r1 << 14);
    }
}

__global__ void __launch_bounds__(1024)
scan_kernel()
{
    __shared__ int s[1024];
    const int t = threadIdx.x;
    const int C = NBINS / 1024;            // 16 bins per thread
    const int base = t * C;
    int local[C];
    int sum = 0;
    #pragma unroll
    for (int j = 0; j < C; j++) { local[j] = g_hist[base + j]; sum += local[j]; }
    s[t] = sum;
    __syncthreads();
    #pragma unroll
    for (int d = 1; d < 1024; d <<= 1) {
        int v = (t >= d) ? s[t - d] : 0;
        __syncthreads();
        if (t >= d) s[t] += v;
        __syncthreads();
    }
    int run = s[t] - sum;
    #pragma unroll
    for (int j = 0; j < C; j++) { g_offs[base + j] = run; run += local[j]; }
}

// Pass 2: NO atomics — pos = offs[bin] + rank.
__global__ void __launch_bounds__(THREADS)
scatter_kernel(const float4* __restrict__ x2)
{
    const int base2 = blockIdx.x * THREADS * (PPT / 2) + threadIdx.x;
    #pragma unroll
    for (int k = 0; k < PPT / 2; k++) {
        const int   i2 = base2 + k * THREADS;
        const float4 v = x2[i2];
        const unsigned e0 = g_rank[i2 * 2];
        const unsigned e1 = g_rank[i2 * 2 + 1];
        const int pos0 = g_offs[e0 & 0x3FFFu] + (int)(e0 >> 14);
        const int pos1 = g_offs[e1 & 0x3FFFu] + (int)(e1 >> 14);
        uint4 r0, r1;
        r0.x = __float_as_uint(v.x); r0.y = __float_as_uint(v.y);
        r0.z = (unsigned)(i2 * 2);   r0.w = 0u;
        r1.x = __float_as_uint(v.z); r1.y = __float_as_uint(v.w);
        r1.z = (unsigned)(i2 * 2 + 1); r1.w = 0u;
        g_pack[pos0] = r0;
        g_pack[pos1] = r1;
    }
}

__device__ __forceinline__ float2 h2f(unsigned u) {
    return __half22float2(*reinterpret_cast<__half2*>(&u));
}

__global__ void __launch_bounds__(THREADS, 2)
grid_linear_kernel(float* __restrict__ out)
{
    extern __shared__ float tr[];   // 16 warps x 32 x 33 floats

    const int tid  = threadIdx.x;
    const int warp = tid >> 5;
    const int lane = tid & 31;
    const int gid  = blockIdx.x * THREADS + tid;

    const uint4 rec = g_pack[gid];
    const float2 p  = make_float2(__uint_as_float(rec.x), __uint_as_float(rec.y));
    const int    oi = (int)rec.z;

    float res[32];

    // Levels 0..14: indices always interior -> single quad load, no edge handling.
    #pragma unroll
    for (int l = 0; l < 15; l++) {
        const float ix = fmaf(p.x, c_A[l], 255.5f);
        const float iy = fmaf(p.y, c_A[l], 255.5f);

        const float x0f = floorf(ix);
        const float y0f = floorf(iy);
        const float wx1 = ix - x0f;
        const float wy1 = iy - y0f;
        const float wx0 = 1.0f - wx1;
        const float wy0 = 1.0f - wy1;

        const int x0 = (int)x0f;
        const int y0 = (int)y0f;

        const uint4 q = __ldg(g_quad + (size_t)l * NN + (y0 * NSIDE + x0));
        const float2 a00 = h2f(q.x), a01 = h2f(q.y);
        const float2 a10 = h2f(q.z), a11 = h2f(q.w);

        const float w00 = wx0 * wy0, w01 = wx1 * wy0;
        const float w10 = wx0 * wy1, w11 = wx1 * wy1;

        res[l]      = a00.x * w00 + a01.x * w01 + a10.x * w10 + a11.x * w11;
        res[16 + l] = a00.y * w00 + a01.y * w01 + a10.y * w10 + a11.y * w11;
    }

    // Level 15: padded 513x513 quad table; stored zeros implement zeros-padding
    // exactly, so plain bilinear weights are correct at every edge.
    {
        const float ix = fmaf(p.x, 256.0f, 255.5f);
        const float iy = fmaf(p.y, 256.0f, 255.5f);

        const float x0f = floorf(ix);
        const float y0f = floorf(iy);
        const float wx1 = ix - x0f;
        const float wy1 = iy - y0f;
        const float wx0 = 1.0f - wx1;
        const float wy0 = 1.0f - wy1;

        const int xi = (int)x0f + 1;   // in [0,512]
        const int yi = (int)y0f + 1;

        const uint4 q = __ldg(g_quad15 + (yi * NP + xi));
        const float2 a00 = h2f(q.x), a01 = h2f(q.y);
        const float2 a10 = h2f(q.z), a11 = h2f(q.w);

        const float w00 = wx0 * wy0, w01 = wx1 * wy0;
        const float w10 = wx0 * wy1, w11 = wx1 * wy1;

        res[15] = a00.x * w00 + a01.x * w01 + a10.x * w10 + a11.x * w11;
        res[31] = a00.y * w00 + a01.y * w01 + a10.y * w10 + a11.y * w11;
    }

    // Transpose in smem, then one coalesced 128B row per original point index.
    float* rowbuf = tr + warp * (32 * 33) + lane * 33;
    #pragma unroll
    for (int i = 0; i < 32; i++) rowbuf[i] = res[i];
    __syncwarp();

    #pragma unroll
    for (int r = 0; r < 32; r++) {
        const int ir = __shfl_sync(0xffffffffu, oi, r);
        __stcs(out + (size_t)ir * 32 + lane, tr[warp * (32 * 33) + r * 33 + lane]);
    }
}

extern "C" void kernel_launch(void* const* d_in, const int* in_sizes, int n_in,
                              void* d_out, int out_size)
{
    const float2* x     = (const float2*)d_in[0];
    const float*  table = (const float*)d_in[1];
    float*        out   = (float*)d_out;

    static void* hist_addr = nullptr;
    static cudaStream_t s1;
    static cudaEvent_t ev_fork, ev_quad;
    static int init_done = 0;
    if (!init_done) {
        cudaGetSymbolAddress(&hist_addr, g_hist);
        cudaFuncSetAttribute(grid_linear_kernel,
                             cudaFuncAttributeMaxDynamicSharedMemorySize,
                             16 * 32 * 33 * (int)sizeof(float));
        cudaStreamCreateWithFlags(&s1, cudaStreamNonBlocking);
        cudaEventCreateWithFlags(&ev_fork, cudaEventDisableTiming);
        cudaEventCreateWithFlags(&ev_quad, cudaEventDisableTiming);
        init_done = 1;
    }

    // Fork: quad-table builds on side stream; sort chain on main stream.
    cudaEventRecord(ev_fork, 0);
    cudaStreamWaitEvent(s1, ev_fork, 0);
    quadify_kernel<<<(15 * NN + 255) / 256, 256, 0, s1>>>(table);
    quadify15_kernel<<<(NP * NP + 255) / 256, 256, 0, s1>>>(table);
    cudaEventRecord(ev_quad, s1);

    cudaMemsetAsync(hist_addr, 0, NBINS * sizeof(int));
    hist_kernel<<<NPTS / (THREADS * PPT), THREADS>>>((const float4*)x);
    scan_kernel<<<1, 1024>>>();
    scatter_kernel<<<NPTS / (THREADS * PPT), THREADS>>>((const float4*)x);

    cudaStreamWaitEvent(0, ev_quad, 0);
    grid_linear_kernel<<<NPTS / THREADS, THREADS, 16 * 32 * 33 * sizeof(float)>>>(out);
}

// round 11
// speedup vs baseline: 2.0651x; 1.0948x over previous
#include <cuda_runtime.h>
#include <cuda_fp16.h>

#define NLEV 16
#define NSIDE 512
#define NP 513            // padded side for level-15 quad table
#define NN (NSIDE * NSIDE)
#define THREADS 512
#define NPTS 1048576
#define NB 128
#define NBINS (NB * NB)
#define PPT 4

__device__ __align__(16) uint4 g_quad[15 * NN];      // levels 0..14
__device__ __align__(16) uint4 g_quad15[NP * NP];    // level 15, padded

__device__ __align__(16) int      g_hist[NBINS];
__device__ __align__(16) int      g_offs[NBINS];
__device__ __align__(16) unsigned g_rank[NPTS];      // bin | (rank << 14)
__device__ __align__(16) uint4    g_pack[NPTS];      // {px, py, orig_idx, pad}

// A_l = 256 * scaler_l ; ix = fmaf(px, A_l, 255.5f)
__device__ __constant__ float c_A[NLEV] = {
      8.0f,  10.0f,  12.5f,  16.0f,  20.0f,  25.0f,  32.0f,  40.0f,
     50.5f,  64.0f,  80.5f, 101.5f, 128.0f, 161.0f, 203.0f, 256.0f
};

__device__ __forceinline__ uint4 make_quad(const float* t0, const float* t1,
                                           int y0, int x0)
{
    auto val = [&](int y, int xx, const float* t) -> float {
        return (y >= 0 && y < NSIDE && xx >= 0 && xx < NSIDE) ? t[y * NSIDE + xx] : 0.0f;
    };
    __half2 ha = __floats2half2_rn(val(y0, x0, t0),         val(y0, x0, t1));
    __half2 hb = __floats2half2_rn(val(y0, x0 + 1, t0),     val(y0, x0 + 1, t1));
    __half2 hc = __floats2half2_rn(val(y0 + 1, x0, t0),     val(y0 + 1, x0, t1));
    __half2 hd = __floats2half2_rn(val(y0 + 1, x0 + 1, t0), val(y0 + 1, x0 + 1, t1));
    uint4 e;
    e.x = *reinterpret_cast<unsigned*>(&ha);
    e.y = *reinterpret_cast<unsigned*>(&hb);
    e.z = *reinterpret_cast<unsigned*>(&hc);
    e.w = *reinterpret_cast<unsigned*>(&hd);
    return e;
}

__global__ void __launch_bounds__(256)
quadify_kernel(const float* __restrict__ table)
{
    int i = blockIdx.x * 256 + threadIdx.x;
    if (i >= 15 * NN) return;
    const int l  = i >> 18;
    const int p  = i & (NN - 1);
    const float* t0 = table + (size_t)(2 * l) * NN;
    g_quad[i] = make_quad(t0, t0 + NN, p >> 9, p & (NSIDE - 1));
}

__global__ void __launch_bounds__(256)
quadify15_kernel(const float* __restrict__ table)
{
    int i = blockIdx.x * 256 + threadIdx.x;
    if (i >= NP * NP) return;
    const int yy = i / NP;
    const int xx = i - yy * NP;
    const float* t0 = table + (size_t)30 * NN;
    g_quad15[i] = make_quad(t0, t0 + NN, yy - 1, xx - 1);
}

__device__ __forceinline__ int point_bin(float px, float py) {
    int bx = (int)((px + 1.0f) * (NB * 0.5f));
    int by = (int)((py + 1.0f) * (NB * 0.5f));
    bx = min(max(bx, 0), NB - 1);
    by = min(max(by, 0), NB - 1);
    return by * NB + bx;
}

// Pass 1: histogram + per-point rank (the atomicAdd return value).
__global__ void __launch_bounds__(THREADS)
hist_kernel(const float4* __restrict__ x2)
{
    const int base = blockIdx.x * THREADS * (PPT / 2) + threadIdx.x;
    #pragma unroll
    for (int k = 0; k < PPT / 2; k++) {
        const int   i2 = base + k * THREADS;
        const float4 v = x2[i2];
        const int b0 = point_bin(v.x, v.y);
        const int b1 = point_bin(v.z, v.w);
        const unsigned r0 = (unsigned)atomicAdd(&g_hist[b0], 1);
        const unsigned r1 = (unsigned)atomicAdd(&g_hist[b1], 1);
        uint2 rr;
        rr.x = (unsigned)b0 | (r0 << 14);
        rr.y = (unsigned)b1 | (r1 << 14);
        *reinterpret_cast<uint2*>(g_rank + i2 * 2) = rr;   // one STG.64
    }
}

// Vectorized 2-barrier scan: 1024 threads x 16 bins (4x int4 each).
__global__ void __launch_bounds__(1024)
scan_kernel()
{
    __shared__ int wsum[32];
    const int t    = threadIdx.x;
    const int lane = t & 31;
    const int wid  = t >> 5;

    const int4* hp = (const int4*)g_hist;
    int4 v[4];
    const int base4 = t * 4;
    #pragma unroll
    for (int j = 0; j < 4; j++) v[j] = hp[base4 + j];

    int pre[4];
    int tot = 0;
    #pragma unroll
    for (int j = 0; j < 4; j++) {
        pre[j] = tot;
        tot += v[j].x + v[j].y + v[j].z + v[j].w;
    }

    // Warp inclusive scan (shuffle, no barriers).
    int inc = tot;
    #pragma unroll
    for (int d = 1; d < 32; d <<= 1) {
        int n = __shfl_up_sync(0xffffffffu, inc, d);
        if (lane >= d) inc += n;
    }
    if (lane == 31) wsum[wid] = inc;
    __syncthreads();
    if (wid == 0) {
        int w = wsum[lane];
        #pragma unroll
        for (int d = 1; d < 32; d <<= 1) {
            int n = __shfl_up_sync(0xffffffffu, w, d);
            if (lane >= d) w += n;
        }
        wsum[lane] = w;
    }
    __syncthreads();

    const int warp_excl   = (wid > 0) ? wsum[wid - 1] : 0;
    const int thread_excl = warp_excl + (inc - tot);

    int4* op = (int4*)g_offs;
    #pragma unroll
    for (int j = 0; j < 4; j++) {
        const int s = thread_excl + pre[j];
        int4 o;
        o.x = s;
        o.y = s + v[j].x;
        o.z = s + v[j].x + v[j].y;
        o.w = s + v[j].x + v[j].y + v[j].z;
        op[base4 + j] = o;
    }
}

// Pass 2: NO atomics — pos = offs[bin] + rank.
__global__ void __launch_bounds__(THREADS)
scatter_kernel(const float4* __restrict__ x2)
{
    const int base2 = blockIdx.x * THREADS * (PPT / 2) + threadIdx.x;
    #pragma unroll
    for (int k = 0; k < PPT / 2; k++) {
        const int   i2 = base2 + k * THREADS;
        const float4 v = x2[i2];
        const uint2 e  = *reinterpret_cast<const uint2*>(g_rank + i2 * 2);
        const int pos0 = g_offs[e.x & 0x3FFFu] + (int)(e.x >> 14);
        const int pos1 = g_offs[e.y & 0x3FFFu] + (int)(e.y >> 14);
        uint4 r0, r1;
        r0.x = __float_as_uint(v.x); r0.y = __float_as_uint(v.y);
        r0.z = (unsigned)(i2 * 2);   r0.w = 0u;
        r1.x = __float_as_uint(v.z); r1.y = __float_as_uint(v.w);
        r1.z = (unsigned)(i2 * 2 + 1); r1.w = 0u;
        g_pack[pos0] = r0;
        g_pack[pos1] = r1;
    }
}

__device__ __forceinline__ float2 h2f(unsigned u) {
    return __half22float2(*reinterpret_cast<__half2*>(&u));
}

__global__ void __launch_bounds__(THREADS, 2)
grid_linear_kernel(float* __restrict__ out)
{
    extern __shared__ float tr[];   // 16 warps x 32 x 33 floats

    const int tid  = threadIdx.x;
    const int warp = tid >> 5;
    const int lane = tid & 31;
    const int gid  = blockIdx.x * THREADS + tid;

    const uint4 rec = g_pack[gid];
    const float2 p  = make_float2(__uint_as_float(rec.x), __uint_as_float(rec.y));
    const int    oi = (int)rec.z;

    float res[32];

    // Levels 0..14: indices always interior -> single quad load, no edge handling.
    #pragma unroll
    for (int l = 0; l < 15; l++) {
        const float ix = fmaf(p.x, c_A[l], 255.5f);
        const float iy = fmaf(p.y, c_A[l], 255.5f);

        const float x0f = floorf(ix);
        const float y0f = floorf(iy);
        const float wx1 = ix - x0f;
        const float wy1 = iy - y0f;
        const float wx0 = 1.0f - wx1;
        const float wy0 = 1.0f - wy1;

        const int x0 = (int)x0f;
        const int y0 = (int)y0f;

        const uint4 q = __ldg(g_quad + (size_t)l * NN + (y0 * NSIDE + x0));
        const float2 a00 = h2f(q.x), a01 = h2f(q.y);
        const float2 a10 = h2f(q.z), a11 = h2f(q.w);

        const float w00 = wx0 * wy0, w01 = wx1 * wy0;
        const float w10 = wx0 * wy1, w11 = wx1 * wy1;

        res[l]      = a00.x * w00 + a01.x * w01 + a10.x * w10 + a11.x * w11;
        res[16 + l] = a00.y * w00 + a01.y * w01 + a10.y * w10 + a11.y * w11;
    }

    // Level 15: padded 513x513 quad table; stored zeros implement zeros-padding.
    {
        const float ix = fmaf(p.x, 256.0f, 255.5f);
        const float iy = fmaf(p.y, 256.0f, 255.5f);

        const float x0f = floorf(ix);
        const float y0f = floorf(iy);
        const float wx1 = ix - x0f;
        const float wy1 = iy - y0f;
        const float wx0 = 1.0f - wx1;
        const float wy0 = 1.0f - wy1;

        const int xi = (int)x0f + 1;   // in [0,512]
        const int yi = (int)y0f + 1;

        const uint4 q = __ldg(g_quad15 + (yi * NP + xi));
        const float2 a00 = h2f(q.x), a01 = h2f(q.y);
        const float2 a10 = h2f(q.z), a11 = h2f(q.w);

        const float w00 = wx0 * wy0, w01 = wx1 * wy0;
        const float w10 = wx0 * wy1, w11 = wx1 * wy1;

        res[15] = a00.x * w00 + a01.x * w01 + a10.x * w10 + a11.x * w11;
        res[31] = a00.y * w00 + a01.y * w01 + a10.y * w10 + a11.y * w11;
    }

    // Transpose in smem, then one coalesced 128B row per original point index.
    float* rowbuf = tr + warp * (32 * 33) + lane * 33;
    #pragma unroll
    for (int i = 0; i < 32; i++) rowbuf[i] = res[i];
    __syncwarp();

    #pragma unroll
    for (int r = 0; r < 32; r++) {
        const int ir = __shfl_sync(0xffffffffu, oi, r);
        __stcs(out + (size_t)ir * 32 + lane, tr[warp * (32 * 33) + r * 33 + lane]);
    }
}

extern "C" void kernel_launch(void* const* d_in, const int* in_sizes, int n_in,
                              void* d_out, int out_size)
{
    const float2* x     = (const float2*)d_in[0];
    const float*  table = (const float*)d_in[1];
    float*        out   = (float*)d_out;

    static void* hist_addr = nullptr;
    static cudaStream_t s1;
    static cudaEvent_t ev_fork, ev_quad;
    static int init_done = 0;
    if (!init_done) {
        cudaGetSymbolAddress(&hist_addr, g_hist);
        cudaFuncSetAttribute(grid_linear_kernel,
                             cudaFuncAttributeMaxDynamicSharedMemorySize,
                             16 * 32 * 33 * (int)sizeof(float));
        cudaStreamCreateWithFlags(&s1, cudaStreamNonBlocking);
        cudaEventCreateWithFlags(&ev_fork, cudaEventDisableTiming);
        cudaEventCreateWithFlags(&ev_quad, cudaEventDisableTiming);
        init_done = 1;
    }

    // Fork: quad-table builds on side stream; sort chain on main stream.
    cudaEventRecord(ev_fork, 0);
    cudaStreamWaitEvent(s1, ev_fork, 0);
    quadify_kernel<<<(15 * NN + 255) / 256, 256, 0, s1>>>(table);
    quadify15_kernel<<<(NP * NP + 255) / 256, 256, 0, s1>>>(table);
    cudaEventRecord(ev_quad, s1);

    cudaMemsetAsync(hist_addr, 0, NBINS * sizeof(int));
    hist_kernel<<<NPTS / (THREADS * PPT), THREADS>>>((const float4*)x);
    scan_kernel<<<1, 1024>>>();
    scatter_kernel<<<NPTS / (THREADS * PPT), THREADS>>>((const float4*)x);

    cudaStreamWaitEvent(0, ev_quad, 0);
    grid_linear_kernel<<<NPTS / THREADS, THREADS, 16 * 32 * 33 * sizeof(float)>>>(out);
}